// round 4
// baseline (speedup 1.0000x reference)
#include <cuda_runtime.h>

#define NCH        30
#define COORDW     5.0f
#define NOOBJW     0.5f
#define TPB        128
#define CELLS_PB   120
#define TILE_FLOATS (CELLS_PB * NCH)          // 3600 per array
#define TILE_F4     (TILE_FLOATS / 4)         // 900
#define STAGE_FLOATS (2 * TILE_FLOATS)        // sd + sl = 7200
#define SMEM_FLOATS  (2 * STAGE_FLOATS)       // 2 stages = 14400
#define SMEM_BYTES   (SMEM_FLOATS * 4)        // 57600 -> 4 blocks/SM
#define MAXGRID    1024

__device__ float        g_partials[MAXGRID];
__device__ unsigned int g_count = 0;

__device__ __forceinline__ void cp16(float4* smem_dst, const float4* gmem_src) {
    unsigned int s = (unsigned int)__cvta_generic_to_shared(smem_dst);
    asm volatile("cp.async.cg.shared.global [%0], [%1], 16;\n" :: "r"(s), "l"(gmem_src));
}
__device__ __forceinline__ void cp_commit() {
    asm volatile("cp.async.commit_group;\n");
}
__device__ __forceinline__ void cp_wait1() {
    asm volatile("cp.async.wait_group 1;\n");
}
__device__ __forceinline__ void cp_wait0() {
    asm volatile("cp.async.wait_group 0;\n");
}

__device__ __forceinline__ float warp_reduce(float v) {
    #pragma unroll
    for (int o = 16; o > 0; o >>= 1)
        v += __shfl_xor_sync(0xffffffffu, v, o);
    return v;
}

__device__ __forceinline__ void corners(float x, float y, float w, float h,
                                        float r, float c,
                                        float& x1, float& y1, float& x2, float& y2) {
    float cx = (x + c) * (1.0f / 7.0f);
    float cy = (y + r) * (1.0f / 7.0f);
    x1 = cx - w * 0.5f;
    y1 = cy - h * 0.5f;
    x2 = cx + w * 0.5f;
    y2 = cy + h * 0.5f;
}

__device__ __forceinline__ float iou(float ax1, float ay1, float ax2, float ay2,
                                     float bx1, float by1, float bx2, float by2) {
    float iw = fmaxf(fminf(ax2, bx2) - fmaxf(ax1, bx1), 0.0f);
    float ih = fmaxf(fminf(ay2, by2) - fmaxf(ay1, by1), 0.0f);
    float inter = iw * ih;
    float area_a = (ax2 - ax1) * (ay2 - ay1);
    float area_b = (bx2 - bx1) * (by2 - by1);
    float uni = area_a + area_b - inter;
    return (uni > 0.0f) ? inter / uni : 0.0f;
}

// cell loss from float2-aligned pointers (smem or gmem)
__device__ __forceinline__ float cell_loss2(const float2* __restrict__ dp,
                                            const float2* __restrict__ lp,
                                            float r, float c) {
    float2 d01 = dp[0], d23 = dp[1], d45 = dp[2], d67 = dp[3], d89 = dp[4];
    float2 l01 = lp[0], l23 = lp[1], l45 = lp[2], l67 = lp[3], l89 = lp[4];

    float b1x1, b1y1, b1x2, b1y2;
    float b2x1, b2y1, b2x2, b2y2;
    float gx1,  gy1,  gx2,  gy2;
    corners(d01.x, d01.y, d23.x, d23.y, r, c, b1x1, b1y1, b1x2, b1y2);
    corners(d45.y, d67.x, d67.y, d89.x, r, c, b2x1, b2y1, b2x2, b2y2);
    corners(l01.x, l01.y, l23.x, l23.y, r, c, gx1,  gy1,  gx2,  gy2);

    float iou1 = iou(b1x1, b1y1, b1x2, b1y2, gx1, gy1, gx2, gy2);
    float iou2 = iou(b2x1, b2y1, b2x2, b2y2, gx1, gy1, gx2, gy2);
    bool resp1 = (iou1 >= iou2);

    float dx1 = d01.x - l01.x, dy1 = d01.y - l01.y;
    float dx2 = d45.y - l45.y, dy2 = d67.x - l67.x;
    float xy1 = dx1 * dx1 + dy1 * dy1;
    float xy2 = dx2 * dx2 + dy2 * dy2;

    float sw1 = sqrtf(d23.x) - sqrtf(l23.x);
    float sh1 = sqrtf(d23.y) - sqrtf(l23.y);
    float sw2 = sqrtf(d67.y) - sqrtf(l67.y);
    float sh2 = sqrtf(d89.x) - sqrtf(l89.x);
    float wh1 = sw1 * sw1 + sh1 * sh1;
    float wh2 = sw2 * sw2 + sh2 * sh2;

    float d4 = d45.x, d9 = d89.y;

    float co    = COORDW * (resp1 ? xy1 : xy2);
    float wh    = COORDW * (resp1 ? wh1 : wh2);
    float cdiff = resp1 ? (d4 - iou1) : (d9 - iou2);
    float confi = cdiff * cdiff;
    float nin   = NOOBJW * (resp1 ? d9 * d9 : d4 * d4);

    // classes: channels 10..29 = float2 indices 5..14, accumulate on the fly
    float cls = 0.0f;
    #pragma unroll
    for (int i = 5; i < 15; i++) {
        float2 a = dp[i], b = lp[i];
        float ex = a.x - b.x;
        float ey = a.y - b.y;
        cls += ex * ex + ey * ey;
    }

    float m = (l45.x == 1.0f) ? 1.0f : 0.0f;
    float obj_loss   = m * (co + wh + confi + nin + cls);
    float noobj_loss = (1.0f - m) * NOOBJW * (d4 * d4 + d9 * d9);
    return obj_loss + noobj_loss;
}

// stage one full tile into smem buffers via cp.async (caller commits)
__device__ __forceinline__ void stage_tile(const float* __restrict__ data,
                                           const float* __restrict__ labels,
                                           int tile, float* sbuf, int tid) {
    const float4* d4 = reinterpret_cast<const float4*>(data)   + (size_t)tile * TILE_F4;
    const float4* l4 = reinterpret_cast<const float4*>(labels) + (size_t)tile * TILE_F4;
    float4* sd4 = reinterpret_cast<float4*>(sbuf);
    float4* sl4 = reinterpret_cast<float4*>(sbuf + TILE_FLOATS);
    #pragma unroll
    for (int i = 0; i < 8; i++) {
        int idx = i * TPB + tid;
        if (idx < TILE_F4) {
            cp16(sd4 + idx, d4 + idx);
            cp16(sl4 + idx, l4 + idx);
        }
    }
}

__global__ void __launch_bounds__(TPB, 4)
yolo_loss_pipe(const float* __restrict__ data,
               const float* __restrict__ labels,
               float* __restrict__ out,
               int ncells, float invB, int ntiles) {
    extern __shared__ float smem[];   // [2][STAGE_FLOATS]
    __shared__ float sred[TPB / 32];
    __shared__ bool  s_last;

    const int tid = threadIdx.x;
    const int lane = tid & 31;
    const int warp = tid >> 5;
    const int gstride = gridDim.x;

    float acc = 0.0f;

    int tile = blockIdx.x;
    bool first_full = (tile < ntiles) && (tile * CELLS_PB + CELLS_PB <= ncells);
    if (first_full)
        stage_tile(data, labels, tile, smem, tid);
    cp_commit();

    int it = 0;
    while (tile < ntiles) {
        int next = tile + gstride;
        bool next_full = (next < ntiles) && (next * CELLS_PB + CELLS_PB <= ncells);
        bool cur_full  = (tile * CELLS_PB + CELLS_PB <= ncells);

        if (next_full)
            stage_tile(data, labels, next, smem + ((it + 1) & 1) * STAGE_FLOATS, tid);
        cp_commit();

        cp_wait1();          // current tile's copy complete
        __syncthreads();

        if (cur_full) {
            if (tid < CELLS_PB) {
                const float* sd = smem + (it & 1) * STAGE_FLOATS;
                const float* sl = sd + TILE_FLOATS;
                int cell = tile * CELLS_PB + tid;
                int within = cell % 49;
                float r = (float)(within / 7);
                float c = (float)(within % 7);
                acc += cell_loss2(reinterpret_cast<const float2*>(sd) + tid * 15,
                                  reinterpret_cast<const float2*>(sl) + tid * 15,
                                  r, c);
            }
        } else {
            // partial tail tile: direct global loads (one-off)
            int cell = tile * CELLS_PB + tid;
            if (tid < CELLS_PB && cell < ncells) {
                int within = cell % 49;
                float r = (float)(within / 7);
                float c = (float)(within % 7);
                acc += cell_loss2(reinterpret_cast<const float2*>(data)   + (size_t)cell * 15,
                                  reinterpret_cast<const float2*>(labels) + (size_t)cell * 15,
                                  r, c);
            }
        }
        __syncthreads();     // buffer (it&1) free for reuse
        tile = next;
        it++;
    }
    cp_wait0();

    // deterministic block reduction
    float v = warp_reduce(acc);
    if (lane == 0) sred[warp] = v;
    __syncthreads();
    if (tid == 0) {
        float s = sred[0] + sred[1] + sred[2] + sred[3];
        g_partials[blockIdx.x] = s;
        __threadfence();
        unsigned int t = atomicAdd(&g_count, 1u);
        s_last = (t == (unsigned int)(gridDim.x - 1));
    }
    __syncthreads();

    if (s_last) {
        float s = 0.0f;
        for (int i = tid; i < (int)gridDim.x; i += TPB)
            s += g_partials[i];
        float w = warp_reduce(s);
        if (lane == 0) sred[warp] = w;
        __syncthreads();
        if (tid == 0) {
            float tot = sred[0] + sred[1] + sred[2] + sred[3];
            out[0] = tot * invB;
            g_count = 0;   // reset for next graph replay
        }
    }
}

extern "C" void kernel_launch(void* const* d_in, const int* in_sizes, int n_in,
                              void* d_out, int out_size) {
    const float* data   = (const float*)d_in[0];
    const float* labels = (const float*)d_in[1];
    float* out = (float*)d_out;

    int total  = in_sizes[0];           // B*7*7*30
    int ncells = total / NCH;           // B*49
    int B      = ncells / 49;

    int ntiles = (ncells + CELLS_PB - 1) / CELLS_PB;    // 3346 for B=8192
    int grid   = 592;                                    // 148 SM x 4 blocks
    if (grid > ntiles) grid = ntiles;
    if (grid > MAXGRID) grid = MAXGRID;

    cudaFuncSetAttribute(yolo_loss_pipe,
                         cudaFuncAttributeMaxDynamicSharedMemorySize, SMEM_BYTES);

    yolo_loss_pipe<<<grid, TPB, SMEM_BYTES>>>(data, labels, out,
                                              ncells, 1.0f / (float)B, ntiles);
}

// round 5
// speedup vs baseline: 1.2003x; 1.2003x over previous
#include <cuda_runtime.h>

#define NCH        30
#define COORDW     5.0f
#define NOOBJW     0.5f
#define TPB        128
#define CELLS_PB   128
#define TILE_FLOATS (CELLS_PB * NCH)          // 3840 per array
#define TILE_F4     (TILE_FLOATS / 4)         // 960
#define STAGE_FLOATS (2 * TILE_FLOATS)        // sd + sl = 7680
#define NSTAGE      3
#define SMEM_FLOATS (NSTAGE * STAGE_FLOATS)   // 23040
#define SMEM_BYTES  (SMEM_FLOATS * 4)         // 92160 -> 2 blocks/SM (incl 1KB reserve)
#define MAXGRID    1024

__device__ float        g_partials[MAXGRID];
__device__ unsigned int g_count = 0;

__device__ __forceinline__ void cp16(float4* smem_dst, const float4* gmem_src) {
    unsigned int s = (unsigned int)__cvta_generic_to_shared(smem_dst);
    asm volatile("cp.async.cg.shared.global [%0], [%1], 16;\n" :: "r"(s), "l"(gmem_src));
}
__device__ __forceinline__ void cp_commit() {
    asm volatile("cp.async.commit_group;\n");
}
__device__ __forceinline__ void cp_wait2() {
    asm volatile("cp.async.wait_group 2;\n");
}
__device__ __forceinline__ void cp_wait0() {
    asm volatile("cp.async.wait_group 0;\n");
}

__device__ __forceinline__ float warp_reduce(float v) {
    #pragma unroll
    for (int o = 16; o > 0; o >>= 1)
        v += __shfl_xor_sync(0xffffffffu, v, o);
    return v;
}

__device__ __forceinline__ void corners(float x, float y, float w, float h,
                                        float r, float c,
                                        float& x1, float& y1, float& x2, float& y2) {
    float cx = (x + c) * (1.0f / 7.0f);
    float cy = (y + r) * (1.0f / 7.0f);
    x1 = cx - w * 0.5f;
    y1 = cy - h * 0.5f;
    x2 = cx + w * 0.5f;
    y2 = cy + h * 0.5f;
}

__device__ __forceinline__ float iou(float ax1, float ay1, float ax2, float ay2,
                                     float bx1, float by1, float bx2, float by2) {
    float iw = fmaxf(fminf(ax2, bx2) - fmaxf(ax1, bx1), 0.0f);
    float ih = fmaxf(fminf(ay2, by2) - fmaxf(ay1, by1), 0.0f);
    float inter = iw * ih;
    float area_a = (ax2 - ax1) * (ay2 - ay1);
    float area_b = (bx2 - bx1) * (by2 - by1);
    float uni = area_a + area_b - inter;
    return (uni > 0.0f) ? __fdividef(inter, uni) : 0.0f;
}

// cell loss from float2-aligned pointers (smem or gmem)
__device__ __forceinline__ float cell_loss2(const float2* __restrict__ dp,
                                            const float2* __restrict__ lp,
                                            float r, float c) {
    float2 d01 = dp[0], d23 = dp[1], d45 = dp[2], d67 = dp[3], d89 = dp[4];
    float2 l01 = lp[0], l23 = lp[1], l45 = lp[2], l67 = lp[3], l89 = lp[4];

    float b1x1, b1y1, b1x2, b1y2;
    float b2x1, b2y1, b2x2, b2y2;
    float gx1,  gy1,  gx2,  gy2;
    corners(d01.x, d01.y, d23.x, d23.y, r, c, b1x1, b1y1, b1x2, b1y2);
    corners(d45.y, d67.x, d67.y, d89.x, r, c, b2x1, b2y1, b2x2, b2y2);
    corners(l01.x, l01.y, l23.x, l23.y, r, c, gx1,  gy1,  gx2,  gy2);

    float iou1 = iou(b1x1, b1y1, b1x2, b1y2, gx1, gy1, gx2, gy2);
    float iou2 = iou(b2x1, b2y1, b2x2, b2y2, gx1, gy1, gx2, gy2);
    bool resp1 = (iou1 >= iou2);

    float dx1 = d01.x - l01.x, dy1 = d01.y - l01.y;
    float dx2 = d45.y - l45.y, dy2 = d67.x - l67.x;
    float xy1 = dx1 * dx1 + dy1 * dy1;
    float xy2 = dx2 * dx2 + dy2 * dy2;

    float sw1 = sqrtf(d23.x) - sqrtf(l23.x);
    float sh1 = sqrtf(d23.y) - sqrtf(l23.y);
    float sw2 = sqrtf(d67.y) - sqrtf(l67.y);
    float sh2 = sqrtf(d89.x) - sqrtf(l89.x);
    float wh1 = sw1 * sw1 + sh1 * sh1;
    float wh2 = sw2 * sw2 + sh2 * sh2;

    float d4 = d45.x, d9 = d89.y;

    float co    = COORDW * (resp1 ? xy1 : xy2);
    float wh    = COORDW * (resp1 ? wh1 : wh2);
    float cdiff = resp1 ? (d4 - iou1) : (d9 - iou2);
    float confi = cdiff * cdiff;
    float nin   = NOOBJW * (resp1 ? d9 * d9 : d4 * d4);

    float cls = 0.0f;
    #pragma unroll
    for (int i = 5; i < 15; i++) {
        float2 a = dp[i], b = lp[i];
        float ex = a.x - b.x;
        float ey = a.y - b.y;
        cls += ex * ex + ey * ey;
    }

    float m = (l45.x == 1.0f) ? 1.0f : 0.0f;
    float obj_loss   = m * (co + wh + confi + nin + cls);
    float noobj_loss = (1.0f - m) * NOOBJW * (d4 * d4 + d9 * d9);
    return obj_loss + noobj_loss;
}

// stage one full tile into an smem stage via cp.async (caller commits)
__device__ __forceinline__ void stage_tile(const float* __restrict__ data,
                                           const float* __restrict__ labels,
                                           int tile, float* sbuf, int tid) {
    const float4* d4 = reinterpret_cast<const float4*>(data)   + (size_t)tile * TILE_F4;
    const float4* l4 = reinterpret_cast<const float4*>(labels) + (size_t)tile * TILE_F4;
    float4* sd4 = reinterpret_cast<float4*>(sbuf);
    float4* sl4 = reinterpret_cast<float4*>(sbuf + TILE_FLOATS);
    #pragma unroll
    for (int i = 0; i < 8; i++) {
        int idx = i * TPB + tid;
        if (idx < TILE_F4) {
            cp16(sd4 + idx, d4 + idx);
            cp16(sl4 + idx, l4 + idx);
        }
    }
}

__global__ void __launch_bounds__(TPB, 2)
yolo_loss_pipe3(const float* __restrict__ data,
                const float* __restrict__ labels,
                float* __restrict__ out,
                int ncells, float invB, int ntiles) {
    extern __shared__ float smem[];   // [NSTAGE][STAGE_FLOATS]
    __shared__ float sred[TPB / 32];
    __shared__ bool  s_last;

    const int tid = threadIdx.x;
    const int lane = tid & 31;
    const int warp = tid >> 5;
    const int gstride = gridDim.x;

    float acc = 0.0f;

    // prologue: stage tiles t0, t1 into stages 0, 1 as two groups
    int t0 = blockIdx.x;
    if (t0 < ntiles && t0 * CELLS_PB + CELLS_PB <= ncells)
        stage_tile(data, labels, t0, smem, tid);
    cp_commit();
    int t1 = t0 + gstride;
    if (t1 < ntiles && t1 * CELLS_PB + CELLS_PB <= ncells)
        stage_tile(data, labels, t1, smem + STAGE_FLOATS, tid);
    cp_commit();

    int it = 0;
    int tile = t0;
    while (tile < ntiles) {
        int t2 = tile + 2 * gstride;
        int s2 = (it + 2) % NSTAGE;
        if (t2 < ntiles && t2 * CELLS_PB + CELLS_PB <= ncells)
            stage_tile(data, labels, t2, smem + s2 * STAGE_FLOATS, tid);
        cp_commit();

        cp_wait2();          // current tile's group complete (<=2 outstanding)
        __syncthreads();

        bool cur_full = (tile * CELLS_PB + CELLS_PB <= ncells);
        if (cur_full) {
            const float* sd = smem + (it % NSTAGE) * STAGE_FLOATS;
            const float* sl = sd + TILE_FLOATS;
            int cell = tile * CELLS_PB + tid;
            int within = cell % 49;
            float r = (float)(within / 7);
            float c = (float)(within % 7);
            acc += cell_loss2(reinterpret_cast<const float2*>(sd) + tid * 15,
                              reinterpret_cast<const float2*>(sl) + tid * 15,
                              r, c);
        } else {
            int cell = tile * CELLS_PB + tid;
            if (cell < ncells) {
                int within = cell % 49;
                float r = (float)(within / 7);
                float c = (float)(within % 7);
                acc += cell_loss2(reinterpret_cast<const float2*>(data)   + (size_t)cell * 15,
                                  reinterpret_cast<const float2*>(labels) + (size_t)cell * 15,
                                  r, c);
            }
        }
        __syncthreads();     // stage (it%3) now free; next iter copies into it
        tile += gstride;
        it++;
    }
    cp_wait0();

    // deterministic block reduction
    float v = warp_reduce(acc);
    if (lane == 0) sred[warp] = v;
    __syncthreads();
    if (tid == 0) {
        float s = sred[0] + sred[1] + sred[2] + sred[3];
        g_partials[blockIdx.x] = s;
        __threadfence();
        unsigned int t = atomicAdd(&g_count, 1u);
        s_last = (t == (unsigned int)(gridDim.x - 1));
    }
    __syncthreads();

    if (s_last) {
        float s = 0.0f;
        for (int i = tid; i < (int)gridDim.x; i += TPB)
            s += g_partials[i];
        float w = warp_reduce(s);
        if (lane == 0) sred[warp] = w;
        __syncthreads();
        if (tid == 0) {
            float tot = sred[0] + sred[1] + sred[2] + sred[3];
            out[0] = tot * invB;
            g_count = 0;   // reset for next graph replay
        }
    }
}

extern "C" void kernel_launch(void* const* d_in, const int* in_sizes, int n_in,
                              void* d_out, int out_size) {
    const float* data   = (const float*)d_in[0];
    const float* labels = (const float*)d_in[1];
    float* out = (float*)d_out;

    int total  = in_sizes[0];           // B*7*7*30
    int ncells = total / NCH;           // B*49
    int B      = ncells / 49;

    int ntiles = (ncells + CELLS_PB - 1) / CELLS_PB;    // 3136 for B=8192
    int grid   = 296;                                    // 148 SM x 2 blocks (92KB smem each)
    if (grid > ntiles) grid = ntiles;
    if (grid > MAXGRID) grid = MAXGRID;

    cudaFuncSetAttribute(yolo_loss_pipe3,
                         cudaFuncAttributeMaxDynamicSharedMemorySize, SMEM_BYTES);

    yolo_loss_pipe3<<<grid, TPB, SMEM_BYTES>>>(data, labels, out,
                                               ncells, 1.0f / (float)B, ntiles);
}

// round 6
// speedup vs baseline: 1.3643x; 1.1366x over previous
#include <cuda_runtime.h>
#include <cstdint>

#define NCH        30
#define COORDW     5.0f
#define NOOBJW     0.5f
#define TPB        128
#define CELLS_PB   128
#define TILE_FLOATS (CELLS_PB * NCH)          // 3840 floats per array
#define TILE_BYTES  (TILE_FLOATS * 4)         // 15360 B per array
#define STAGE_FLOATS (2 * TILE_FLOATS)        // data + labels = 7680 floats
#define STAGE_BYTES  (STAGE_FLOATS * 4)       // 30720 B
#define NSTAGE      3
#define SMEM_BYTES  (NSTAGE * STAGE_BYTES)    // 92160 -> 2 blocks/SM
#define MAXGRID    1024

__device__ float        g_partials[MAXGRID];
__device__ unsigned int g_count = 0;

__device__ __forceinline__ uint32_t smem_u32(const void* p) {
    return (uint32_t)__cvta_generic_to_shared(p);
}

__device__ __forceinline__ void mbar_init(uint32_t mbar, uint32_t count) {
    asm volatile("mbarrier.init.shared.b64 [%0], %1;" :: "r"(mbar), "r"(count) : "memory");
}
__device__ __forceinline__ void mbar_expect_tx(uint32_t mbar, uint32_t bytes) {
    asm volatile("mbarrier.arrive.expect_tx.shared.b64 _, [%0], %1;"
                 :: "r"(mbar), "r"(bytes) : "memory");
}
__device__ __forceinline__ void mbar_wait(uint32_t mbar, uint32_t parity) {
    uint32_t done;
    asm volatile(
        "{\n\t"
        ".reg .pred p;\n\t"
        "mbarrier.try_wait.parity.acquire.cta.shared::cta.b64 p, [%1], %2;\n\t"
        "selp.b32 %0, 1, 0, p;\n\t"
        "}" : "=r"(done) : "r"(mbar), "r"(parity) : "memory");
    if (!done) {
        asm volatile(
            "{\n\t"
            ".reg .pred P1;\n\t"
            "WL_%=:\n\t"
            "mbarrier.try_wait.parity.acquire.cta.shared::cta.b64 P1, [%0], %1, 0x989680;\n\t"
            "@P1 bra.uni WD_%=;\n\t"
            "bra.uni WL_%=;\n\t"
            "WD_%=:\n\t"
            "}" :: "r"(mbar), "r"(parity) : "memory");
    }
}
__device__ __forceinline__ void bulk_g2s(uint32_t sdst, const void* gsrc,
                                         uint32_t bytes, uint32_t mbar) {
    asm volatile(
        "cp.async.bulk.shared::cta.global.mbarrier::complete_tx::bytes [%0], [%1], %2, [%3];"
        :: "r"(sdst), "l"(gsrc), "r"(bytes), "r"(mbar) : "memory");
}

__device__ __forceinline__ float warp_reduce(float v) {
    #pragma unroll
    for (int o = 16; o > 0; o >>= 1)
        v += __shfl_xor_sync(0xffffffffu, v, o);
    return v;
}

__device__ __forceinline__ void corners(float x, float y, float w, float h,
                                        float r, float c,
                                        float& x1, float& y1, float& x2, float& y2) {
    float cx = (x + c) * (1.0f / 7.0f);
    float cy = (y + r) * (1.0f / 7.0f);
    x1 = cx - w * 0.5f;
    y1 = cy - h * 0.5f;
    x2 = cx + w * 0.5f;
    y2 = cy + h * 0.5f;
}

__device__ __forceinline__ float iou(float ax1, float ay1, float ax2, float ay2,
                                     float bx1, float by1, float bx2, float by2) {
    float iw = fmaxf(fminf(ax2, bx2) - fmaxf(ax1, bx1), 0.0f);
    float ih = fmaxf(fminf(ay2, by2) - fmaxf(ay1, by1), 0.0f);
    float inter = iw * ih;
    float area_a = (ax2 - ax1) * (ay2 - ay1);
    float area_b = (bx2 - bx1) * (by2 - by1);
    float uni = area_a + area_b - inter;
    return (uni > 0.0f) ? __fdividef(inter, uni) : 0.0f;
}

__device__ __forceinline__ float cell_loss2(const float2* __restrict__ dp,
                                            const float2* __restrict__ lp,
                                            float r, float c) {
    float2 d01 = dp[0], d23 = dp[1], d45 = dp[2], d67 = dp[3], d89 = dp[4];
    float2 l01 = lp[0], l23 = lp[1], l45 = lp[2], l67 = lp[3], l89 = lp[4];

    float b1x1, b1y1, b1x2, b1y2;
    float b2x1, b2y1, b2x2, b2y2;
    float gx1,  gy1,  gx2,  gy2;
    corners(d01.x, d01.y, d23.x, d23.y, r, c, b1x1, b1y1, b1x2, b1y2);
    corners(d45.y, d67.x, d67.y, d89.x, r, c, b2x1, b2y1, b2x2, b2y2);
    corners(l01.x, l01.y, l23.x, l23.y, r, c, gx1,  gy1,  gx2,  gy2);

    float iou1 = iou(b1x1, b1y1, b1x2, b1y2, gx1, gy1, gx2, gy2);
    float iou2 = iou(b2x1, b2y1, b2x2, b2y2, gx1, gy1, gx2, gy2);
    bool resp1 = (iou1 >= iou2);

    float dx1 = d01.x - l01.x, dy1 = d01.y - l01.y;
    float dx2 = d45.y - l45.y, dy2 = d67.x - l67.x;
    float xy1 = dx1 * dx1 + dy1 * dy1;
    float xy2 = dx2 * dx2 + dy2 * dy2;

    float sw1 = sqrtf(d23.x) - sqrtf(l23.x);
    float sh1 = sqrtf(d23.y) - sqrtf(l23.y);
    float sw2 = sqrtf(d67.y) - sqrtf(l67.y);
    float sh2 = sqrtf(d89.x) - sqrtf(l89.x);
    float wh1 = sw1 * sw1 + sh1 * sh1;
    float wh2 = sw2 * sw2 + sh2 * sh2;

    float d4 = d45.x, d9 = d89.y;

    float co    = COORDW * (resp1 ? xy1 : xy2);
    float wh    = COORDW * (resp1 ? wh1 : wh2);
    float cdiff = resp1 ? (d4 - iou1) : (d9 - iou2);
    float confi = cdiff * cdiff;
    float nin   = NOOBJW * (resp1 ? d9 * d9 : d4 * d4);

    float cls = 0.0f;
    #pragma unroll
    for (int i = 5; i < 15; i++) {
        float2 a = dp[i], b = lp[i];
        float ex = a.x - b.x;
        float ey = a.y - b.y;
        cls += ex * ex + ey * ey;
    }

    float m = (l45.x == 1.0f) ? 1.0f : 0.0f;
    float obj_loss   = m * (co + wh + confi + nin + cls);
    float noobj_loss = (1.0f - m) * NOOBJW * (d4 * d4 + d9 * d9);
    return obj_loss + noobj_loss;
}

__global__ void __launch_bounds__(TPB, 2)
yolo_loss_tma(const float* __restrict__ data,
              const float* __restrict__ labels,
              float* __restrict__ out,
              int ncells, float invB, int ntiles) {
    extern __shared__ float smem[];                 // [NSTAGE][STAGE_FLOATS]
    __shared__ __align__(8) uint64_t mbar_s[NSTAGE];
    __shared__ float sred[TPB / 32];
    __shared__ bool  s_last;

    const int tid = threadIdx.x;
    const int lane = tid & 31;
    const int warp = tid >> 5;
    const int gstride = gridDim.x;

    uint32_t mb[NSTAGE];
    #pragma unroll
    for (int s = 0; s < NSTAGE; s++) mb[s] = smem_u32(&mbar_s[s]);

    if (tid == 0) {
        #pragma unroll
        for (int s = 0; s < NSTAGE; s++) mbar_init(mb[s], 1);
    }
    __syncthreads();

    // issue one tile's bulk copy into stage s (tid 0 only, caller guards)
    auto issue = [&](int tile, int s) {
        uint32_t dst = smem_u32(smem + s * STAGE_FLOATS);
        mbar_expect_tx(mb[s], 2 * TILE_BYTES);
        bulk_g2s(dst,              (const char*)data   + (size_t)tile * TILE_BYTES, TILE_BYTES, mb[s]);
        bulk_g2s(dst + TILE_BYTES, (const char*)labels + (size_t)tile * TILE_BYTES, TILE_BYTES, mb[s]);
    };

    float acc = 0.0f;

    // prologue: depth-2 lookahead
    if (tid == 0) {
        int t0 = blockIdx.x;
        if (t0 < ntiles && t0 * CELLS_PB + CELLS_PB <= ncells) issue(t0, 0);
        int t1 = t0 + gstride;
        if (t1 < ntiles && t1 * CELLS_PB + CELLS_PB <= ncells) issue(t1, 1);
    }

    int it = 0;
    int tile = blockIdx.x;
    while (tile < ntiles) {
        bool cur_full = (tile * CELLS_PB + CELLS_PB <= ncells);
        int s = it % NSTAGE;
        uint32_t parity = (uint32_t)((it / NSTAGE) & 1);

        if (cur_full) {
            mbar_wait(mb[s], parity);
            const float* sd = smem + s * STAGE_FLOATS;
            const float* sl = sd + TILE_FLOATS;
            int cell = tile * CELLS_PB + tid;
            int within = cell % 49;
            float r = (float)(within / 7);
            float c = (float)(within % 7);
            acc += cell_loss2(reinterpret_cast<const float2*>(sd) + tid * 15,
                              reinterpret_cast<const float2*>(sl) + tid * 15,
                              r, c);
        } else {
            int cell = tile * CELLS_PB + tid;
            if (cell < ncells) {
                int within = cell % 49;
                float r = (float)(within / 7);
                float c = (float)(within % 7);
                acc += cell_loss2(reinterpret_cast<const float2*>(data)   + (size_t)cell * 15,
                                  reinterpret_cast<const float2*>(labels) + (size_t)cell * 15,
                                  r, c);
            }
        }
        __syncthreads();     // all threads finished reading stage s

        // refill freed stage with tile it+2 (stage (it+2)%3 == s of it-1... = (s+2)%3, freed)
        int tnext = tile + 2 * gstride;
        if (tid == 0 && tnext < ntiles && tnext * CELLS_PB + CELLS_PB <= ncells)
            issue(tnext, (it + 2) % NSTAGE);

        tile += gstride;
        it++;
    }

    // deterministic block reduction
    float v = warp_reduce(acc);
    if (lane == 0) sred[warp] = v;
    __syncthreads();
    if (tid == 0) {
        float s = sred[0] + sred[1] + sred[2] + sred[3];
        g_partials[blockIdx.x] = s;
        __threadfence();
        unsigned int t = atomicAdd(&g_count, 1u);
        s_last = (t == (unsigned int)(gridDim.x - 1));
    }
    __syncthreads();

    if (s_last) {
        float s = 0.0f;
        for (int i = tid; i < (int)gridDim.x; i += TPB)
            s += g_partials[i];
        float w = warp_reduce(s);
        if (lane == 0) sred[warp] = w;
        __syncthreads();
        if (tid == 0) {
            float tot = sred[0] + sred[1] + sred[2] + sred[3];
            out[0] = tot * invB;
            g_count = 0;   // reset for next graph replay
        }
    }
}

extern "C" void kernel_launch(void* const* d_in, const int* in_sizes, int n_in,
                              void* d_out, int out_size) {
    const float* data   = (const float*)d_in[0];
    const float* labels = (const float*)d_in[1];
    float* out = (float*)d_out;

    int total  = in_sizes[0];           // B*7*7*30
    int ncells = total / NCH;           // B*49
    int B      = ncells / 49;

    int ntiles = (ncells + CELLS_PB - 1) / CELLS_PB;    // 3136 for B=8192
    int grid   = 296;                                    // 148 SM x 2 blocks (92KB smem)
    if (grid > ntiles) grid = ntiles;
    if (grid > MAXGRID) grid = MAXGRID;

    cudaFuncSetAttribute(yolo_loss_tma,
                         cudaFuncAttributeMaxDynamicSharedMemorySize, SMEM_BYTES);

    yolo_loss_tma<<<grid, TPB, SMEM_BYTES>>>(data, labels, out,
                                             ncells, 1.0f / (float)B, ntiles);
}